// round 15
// baseline (speedup 1.0000x reference)
#include <cuda_runtime.h>
#include <cuda_bf16.h>
#include <math.h>
#include <stdint.h>

// Problem constants
#define NCTX   4096
#define DMODEL 1024
#define NHEAD  16
#define DHEAD  64
#define DEPTH  4
#define PFX    3072
#define LAT    1024          // NCTX - PFX
#define FFDIM  4096
#define VOCAB  32000
#define INNER  1024          // NHEAD * DHEAD

// ---------------------------------------------------------------------------
// Scratch (static __device__ globals; no runtime allocation)
// ---------------------------------------------------------------------------
__device__ float g_prefix[PFX * DMODEL];
__device__ float g_h     [LAT * DMODEL];
__device__ float g_xn    [LAT * DMODEL];
__device__ float g_kvctx [PFX * 2 * INNER];
__device__ float g_attn  [LAT * INNER];
__device__ float g_ff    [LAT * FFDIM];
__device__ float g_qkv   [LAT * 3 * INNER];

// tf32-rounded weight scratch (one big buffer, float offsets)
#define W_CQKV  0
#define W_WKV   (W_CQKV + DMODEL * 3 * INNER)
#define W_WO    (W_WKV  + DMODEL * 2 * INNER)
#define W_CF1   (W_WO   + INNER * DMODEL)
#define W_CF2   (W_CF1  + DMODEL * FFDIM)
#define W_LQKV  (W_CF2  + FFDIM * DMODEL)
#define W_LWO   (W_LQKV + DEPTH * DMODEL * 3 * INNER)
#define W_LF1   (W_LWO  + DEPTH * INNER * DMODEL)
#define W_LF2   (W_LF1  + DEPTH * DMODEL * FFDIM)
#define W_LOG   (W_LF2  + DEPTH * FFDIM * DMODEL)
#define W_TOTAL (W_LOG  + DMODEL * VOCAB)
__device__ float g_w[W_TOTAL];

// ---------------------------------------------------------------------------
// tf32 rounding helpers
// ---------------------------------------------------------------------------
__device__ __forceinline__ uint32_t f2tf(float x) {
    uint32_t r;
    asm("cvt.rna.tf32.f32 %0, %1;" : "=r"(r) : "f"(x));
    return r;
}
__device__ __forceinline__ float rnd_tf32(float x) {
    return __uint_as_float(f2tf(x));
}

// ---------------------------------------------------------------------------
// Fused multi-segment tf32 rounding. Each block rounds 4096 floats
// (256 thr x 4 float4, MLP=4). Segments are contiguous in dst; block-prefix
// ends e0..e3 select the source. All segment sizes are multiples of 4096.
// ---------------------------------------------------------------------------
__global__ void round_multi_kernel(
    const float* __restrict__ s0, const float* __restrict__ s1,
    const float* __restrict__ s2, const float* __restrict__ s3,
    const float* __restrict__ s4, float* __restrict__ dst,
    int e0, int e1, int e2, int e3)
{
    int b = blockIdx.x;
    const float* src; int rel;
    if      (b < e0) { src = s0; rel = b; }
    else if (b < e1) { src = s1; rel = b - e0; }
    else if (b < e2) { src = s2; rel = b - e1; }
    else if (b < e3) { src = s3; rel = b - e2; }
    else             { src = s4; rel = b - e3; }
    const float4* s4p = reinterpret_cast<const float4*>(src) + (size_t)rel * 1024;
    float4* d4p = reinterpret_cast<float4*>(dst) + (size_t)b * 1024;
    int t = threadIdx.x;
    float4 v[4];
#pragma unroll
    for (int u = 0; u < 4; u++) v[u] = s4p[t + u * 256];
#pragma unroll
    for (int u = 0; u < 4; u++) {
        v[u].x = rnd_tf32(v[u].x); v[u].y = rnd_tf32(v[u].y);
        v[u].z = rnd_tf32(v[u].z); v[u].w = rnd_tf32(v[u].w);
        d4p[t + u * 256] = v[u];
    }
}

// Single-array rounding (used for h -> xn before logits)
__global__ void round_kernel(const float* __restrict__ in,
                             float* __restrict__ out, int n4)
{
    int i0 = blockIdx.x * 1024 + threadIdx.x;
    float4 v[4];
#pragma unroll
    for (int u = 0; u < 4; u++)
        v[u] = reinterpret_cast<const float4*>(in)[i0 + u * 256];
#pragma unroll
    for (int u = 0; u < 4; u++) {
        v[u].x = rnd_tf32(v[u].x); v[u].y = rnd_tf32(v[u].y);
        v[u].z = rnd_tf32(v[u].z); v[u].w = rnd_tf32(v[u].w);
        reinterpret_cast<float4*>(out)[i0 + u * 256] = v[u];
    }
}

// Pack [wq | wkv] -> row-major [DMODEL][3*INNER], tf32-rounded.
__global__ void pack_cqkv_kernel(const float* __restrict__ wq,
                                 const float* __restrict__ wkv,
                                 float* __restrict__ dst)
{
    int i = blockIdx.x * blockDim.x + threadIdx.x;  // over D*3I/4
    if (i >= (DMODEL * 3 * INNER) / 4) return;
    int i4 = i * 4;
    int d = i4 / (3 * INNER);
    int j = i4 % (3 * INNER);
    float4 v;
    if (j < INNER)
        v = *reinterpret_cast<const float4*>(wq + (size_t)d * INNER + j);
    else
        v = *reinterpret_cast<const float4*>(wkv + (size_t)d * 2 * INNER + (j - INNER));
    v.x = rnd_tf32(v.x); v.y = rnd_tf32(v.y);
    v.z = rnd_tf32(v.z); v.w = rnd_tf32(v.w);
    reinterpret_cast<float4*>(dst)[i] = v;
}

// ---------------------------------------------------------------------------
// Embedding (prefix feeds GEMM only -> pre-rounded; h stays fp32)
// ---------------------------------------------------------------------------
__global__ void embed_kernel(const int* __restrict__ x,
                             const float* __restrict__ tok,
                             const float* __restrict__ pos)
{
    int idx = blockIdx.x * blockDim.x + threadIdx.x;
    int n = idx >> 10;
    int d = idx & 1023;
    float v = tok[(size_t)x[n] * DMODEL + d] + pos[idx];
    if (n < PFX) g_prefix[(size_t)n * DMODEL + d] = rnd_tf32(v);
    else         g_h[(size_t)(n - PFX) * DMODEL + d] = v;
}

// ---------------------------------------------------------------------------
// LayerNorm (D=1024); output feeds GEMM A only -> pre-rounded to tf32
// ---------------------------------------------------------------------------
__global__ __launch_bounds__(256) void ln_kernel(
    const float* __restrict__ in, float* __restrict__ out,
    const float* __restrict__ g, const float* __restrict__ b)
{
    int row = blockIdx.x;
    const float* p = in + (size_t)row * DMODEL;
    float vals[4];
    float s = 0.f, s2 = 0.f;
#pragma unroll
    for (int u = 0; u < 4; u++) {
        float v = p[threadIdx.x + u * 256];
        vals[u] = v; s += v; s2 += v * v;
    }
#pragma unroll
    for (int o = 16; o; o >>= 1) {
        s  += __shfl_xor_sync(0xffffffffu, s,  o);
        s2 += __shfl_xor_sync(0xffffffffu, s2, o);
    }
    __shared__ float sh[2][8];
    int wid = threadIdx.x >> 5, lane = threadIdx.x & 31;
    if (lane == 0) { sh[0][wid] = s; sh[1][wid] = s2; }
    __syncthreads();
    s = 0.f; s2 = 0.f;
#pragma unroll
    for (int w = 0; w < 8; w++) { s += sh[0][w]; s2 += sh[1][w]; }
    float mean = s * (1.f / DMODEL);
    float var  = s2 * (1.f / DMODEL) - mean * mean;
    float inv  = rsqrtf(var + 1e-5f);
#pragma unroll
    for (int u = 0; u < 4; u++) {
        int d = threadIdx.x + u * 256;
        out[(size_t)row * DMODEL + d] =
            rnd_tf32((vals[u] - mean) * inv * g[d] + b[d]);
    }
}

// ---------------------------------------------------------------------------
// TF32 tensor-core GEMM with cp.async 3-stage pipeline, BK=32 (unchanged).
// ---------------------------------------------------------------------------
#define BK 32
#define STAGES 3

__device__ __forceinline__ uint32_t smem_u32(const void* p) {
    return static_cast<uint32_t>(__cvta_generic_to_shared(p));
}

__device__ __forceinline__ void mma_tf32(float* d, const uint32_t* a, const uint32_t* b) {
    asm volatile(
        "mma.sync.aligned.m16n8k8.row.col.f32.tf32.tf32.f32 "
        "{%0,%1,%2,%3}, {%4,%5,%6,%7}, {%8,%9}, {%0,%1,%2,%3};"
        : "+f"(d[0]), "+f"(d[1]), "+f"(d[2]), "+f"(d[3])
        : "r"(a[0]), "r"(a[1]), "r"(a[2]), "r"(a[3]), "r"(b[0]), "r"(b[1]));
}

template <int BM, int EPI>
__global__ __launch_bounds__(256, 2) void sgemm_kernel(
    const float* __restrict__ A, const float* __restrict__ B,
    float* __restrict__ C, const float* __restrict__ bias,
    const float* __restrict__ res, int M, int Nn, int K)
{
    constexpr int MF = BM / 32;
    constexpr int AP = BK + 4;    // 36
    constexpr int BP = 136;
    extern __shared__ __align__(16) float smem[];
    float* As = smem;                          // [STAGES][BM][AP]
    float* Bs = smem + STAGES * BM * AP;       // [STAGES][BK][BP]

    const int tid  = threadIdx.x;
    const int lane = tid & 31, wid = tid >> 5;
    const int g = lane >> 2, c = lane & 3;
    const int wm = (wid & 1) * (BM / 2);
    const int wn = (wid >> 1) * 32;
    const int bx = blockIdx.x, by = blockIdx.y;

    const int nt = K / BK;

    auto issue_stage = [&](int kt, int slot) {
        const float* Ag = A + (size_t)(by * BM) * K + kt * BK;
#pragma unroll
        for (int r = 0; r < BM / 32; r++) {
            int ch = tid + r * 256;
            int m = ch >> 3, ko = (ch & 7) << 2;
            uint32_t dst = smem_u32(&As[(slot * BM + m) * AP + ko]);
            const float* src = Ag + (size_t)m * K + ko;
            asm volatile("cp.async.cg.shared.global [%0], [%1], 16;"
                         :: "r"(dst), "l"(src) : "memory");
        }
        const float* Bg = B + (size_t)(kt * BK) * Nn + bx * 128;
#pragma unroll
        for (int r = 0; r < 4; r++) {
            int ch = tid + r * 256;
            int kr = ch >> 5, no = (ch & 31) << 2;
            uint32_t dst = smem_u32(&Bs[(slot * BK + kr) * BP + no]);
            const float* src = Bg + (size_t)kr * Nn + no;
            asm volatile("cp.async.cg.shared.global [%0], [%1], 16;"
                         :: "r"(dst), "l"(src) : "memory");
        }
        asm volatile("cp.async.commit_group;" ::: "memory");
    };

    float acc[MF][4][4];
#pragma unroll
    for (int mf = 0; mf < MF; mf++)
#pragma unroll
        for (int nf = 0; nf < 4; nf++)
#pragma unroll
            for (int i = 0; i < 4; i++) acc[mf][nf][i] = 0.f;

#pragma unroll
    for (int s = 0; s < STAGES - 1; s++) issue_stage(s, s);

    for (int kt = 0; kt < nt; kt++) {
        asm volatile("cp.async.wait_group %0;" :: "n"(STAGES - 2) : "memory");
        __syncthreads();
        if (kt + STAGES - 1 < nt)
            issue_stage(kt + STAGES - 1, (kt + STAGES - 1) % STAGES);
        else
            asm volatile("cp.async.commit_group;" ::: "memory");

        const int slot = kt % STAGES;
        const uint32_t* Asl = reinterpret_cast<const uint32_t*>(&As[slot * BM * AP]);
        const uint32_t* Bsl = reinterpret_cast<const uint32_t*>(&Bs[slot * BK * BP]);

#pragma unroll
        for (int ks = 0; ks < 4; ks++) {
            const int k0 = ks * 8;
            uint32_t af[MF][4], bf[4][2];
#pragma unroll
            for (int mf = 0; mf < MF; mf++) {
                const int mrow = wm + mf * 16 + g;
                af[mf][0] = Asl[(size_t)mrow * AP + k0 + c];
                af[mf][1] = Asl[(size_t)(mrow + 8) * AP + k0 + c];
                af[mf][2] = Asl[(size_t)mrow * AP + k0 + c + 4];
                af[mf][3] = Asl[(size_t)(mrow + 8) * AP + k0 + c + 4];
            }
#pragma unroll
            for (int nf = 0; nf < 4; nf++) {
                const int ncol = wn + nf * 8 + g;
                bf[nf][0] = Bsl[(size_t)(k0 + c) * BP + ncol];
                bf[nf][1] = Bsl[(size_t)(k0 + c + 4) * BP + ncol];
            }
#pragma unroll
            for (int mf = 0; mf < MF; mf++)
#pragma unroll
                for (int nf = 0; nf < 4; nf++)
                    mma_tf32(acc[mf][nf], af[mf], bf[nf]);
        }
    }

#pragma unroll
    for (int mf = 0; mf < MF; mf++) {
#pragma unroll
        for (int nf = 0; nf < 4; nf++) {
            int row = by * BM + wm + mf * 16 + g;
            int col = bx * 128 + wn + nf * 8 + 2 * c;
#pragma unroll
            for (int half = 0; half < 2; half++) {
                int r = row + half * 8;
                float v0 = acc[mf][nf][half * 2 + 0];
                float v1 = acc[mf][nf][half * 2 + 1];
                if (EPI == 1) {
                    v0 += bias[col]     + res[(size_t)r * Nn + col];
                    v1 += bias[col + 1] + res[(size_t)r * Nn + col + 1];
                }
                if (EPI == 2) {
                    v0 += res[(size_t)r * Nn + col];
                    v1 += res[(size_t)r * Nn + col + 1];
                }
                if (EPI == 3) {
                    v0 = 0.5f * v0 * (1.f + erff(v0 * 0.70710678f));
                    v1 = 0.5f * v1 * (1.f + erff(v1 * 0.70710678f));
                    v0 = rnd_tf32(v0);
                    v1 = rnd_tf32(v1);
                }
                float2 o = make_float2(v0, v1);
                *reinterpret_cast<float2*>(C + (size_t)r * Nn + col) = o;
            }
        }
    }
}

// ---------------------------------------------------------------------------
// Tensor-core attention with split-tf32 (unchanged from passing R11/R14).
// ---------------------------------------------------------------------------
#define QP 68
#define KP 40
#define VP 72
#define PP 40
#define ATT_SMEM ((64*QP + 2*64*KP + 2*32*VP + 4*16*PP) * 4)

template <int CROSS>
__global__ __launch_bounds__(128) void attn_kernel(
    const float* __restrict__ qsrc, const float* __restrict__ kvctx,
    float* __restrict__ out)
{
    const int OFF = CROSS ? PFX : 0;
    const int hbase = blockIdx.y * DHEAD;
    const int qbase = blockIdx.x * 64;
    const int wid = threadIdx.x >> 5, lane = threadIdx.x & 31;
    const int g = lane >> 2, c = lane & 3;
    const int ibase = qbase + wid * 16;

    extern __shared__ __align__(16) float sm[];
    float* Qs   = sm;
    float* KThi = Qs   + 64 * QP;
    float* KTlo = KThi + 64 * KP;
    float* Vhi  = KTlo + 64 * KP;
    float* Vlo  = Vhi  + 32 * VP;
    float* Ps   = Vlo  + 32 * VP;

    {
        int qr = threadIdx.x >> 1;
        int half = (threadIdx.x & 1) * 32;
        const float* qp = qsrc + (size_t)(qbase + qr) * 3072 + hbase + half;
        float* dst = Qs + qr * QP + half;
#pragma unroll
        for (int u = 0; u < 8; u++) {
            float4 v = *reinterpret_cast<const float4*>(qp + u * 4);
            dst[u * 4 + 0] = v.x * 0.125f;
            dst[u * 4 + 1] = v.y * 0.125f;
            dst[u * 4 + 2] = v.z * 0.125f;
            dst[u * 4 + 3] = v.w * 0.125f;
        }
    }
    __syncthreads();

    uint32_t qhi[8][4], qlo[8][4];
#pragma unroll
    for (int ks = 0; ks < 8; ks++) {
        const int k0 = ks * 8;
        const int r0 = (wid * 16 + g) * QP, r1 = (wid * 16 + g + 8) * QP;
        float v;
        v = Qs[r0 + k0 + c];     qhi[ks][0] = f2tf(v); qlo[ks][0] = f2tf(v - __uint_as_float(qhi[ks][0]));
        v = Qs[r1 + k0 + c];     qhi[ks][1] = f2tf(v); qlo[ks][1] = f2tf(v - __uint_as_float(qhi[ks][1]));
        v = Qs[r0 + k0 + c + 4]; qhi[ks][2] = f2tf(v); qlo[ks][2] = f2tf(v - __uint_as_float(qhi[ks][2]));
        v = Qs[r1 + k0 + c + 4]; qhi[ks][3] = f2tf(v); qlo[ks][3] = f2tf(v - __uint_as_float(qhi[ks][3]));
    }

    float O[8][4];
#pragma unroll
    for (int nf = 0; nf < 8; nf++)
#pragma unroll
        for (int e = 0; e < 4; e++) O[nf][e] = 0.f;
    float mrow0 = -3.0e38f, mrow1 = -3.0e38f;
    float den0 = 0.f, den1 = 0.f;

    const int ntiles = (qbase + 64 + OFF) / 32;
    float* Pw = Ps + wid * 16 * PP;

    for (int t = 0; t < ntiles; t++) {
        const int jt = t * 32;
        __syncthreads();
        {
            int key = threadIdx.x >> 2;
            int d0  = (threadIdx.x & 3) * 16;
            int j = jt + key;
            const float *kp, *vp;
            if (CROSS && j < PFX) {
                kp = kvctx + (size_t)j * 2048 + hbase;
                vp = kp + INNER;
            } else {
                int jj = CROSS ? j - PFX : j;
                if (jj > LAT - 1) jj = LAT - 1;
                kp = qsrc + (size_t)jj * 3072 + INNER + hbase;
                vp = kp + INNER;
            }
#pragma unroll
            for (int u = 0; u < 4; u++) {
                float4 k4 = *reinterpret_cast<const float4*>(kp + d0 + u * 4);
                float4 v4 = *reinterpret_cast<const float4*>(vp + d0 + u * 4);
                const float ke[4] = {k4.x, k4.y, k4.z, k4.w};
                float4 vh, vl;
                float* vhp = &vh.x; float* vlp = &vl.x;
                const float ve[4] = {v4.x, v4.y, v4.z, v4.w};
#pragma unroll
                for (int e = 0; e < 4; e++) {
                    int d = d0 + u * 4 + e;
                    float khi = rnd_tf32(ke[e]);
                    KThi[d * KP + key] = khi;
                    KTlo[d * KP + key] = rnd_tf32(ke[e] - khi);
                    float vhi = rnd_tf32(ve[e]);
                    vhp[e] = vhi;
                    vlp[e] = rnd_tf32(ve[e] - vhi);
                }
                *reinterpret_cast<float4*>(Vhi + key * VP + d0 + u * 4) = vh;
                *reinterpret_cast<float4*>(Vlo + key * VP + d0 + u * 4) = vl;
            }
        }
        __syncthreads();

        if (jt > ibase + 15 + OFF) continue;

        float Sh[4][4], Sl[4][4];
#pragma unroll
        for (int nf = 0; nf < 4; nf++)
#pragma unroll
            for (int e = 0; e < 4; e++) { Sh[nf][e] = 0.f; Sl[nf][e] = 0.f; }
        const uint32_t* KThu = reinterpret_cast<const uint32_t*>(KThi);
        const uint32_t* KTlu = reinterpret_cast<const uint32_t*>(KTlo);
#pragma unroll
        for (int nf = 0; nf < 4; nf++) {
            const int nn = nf * 8 + g;
#pragma unroll
            for (int ks = 0; ks < 8; ks++) {
                const int k0 = ks * 8;
                uint32_t bh[2], bl[2];
                bh[0] = KThu[(k0 + c) * KP + nn];
                bh[1] = KThu[(k0 + c + 4) * KP + nn];
                bl[0] = KTlu[(k0 + c) * KP + nn];
                bl[1] = KTlu[(k0 + c + 4) * KP + nn];
                mma_tf32(Sh[nf], qhi[ks], bh);
                mma_tf32(Sl[nf], qlo[ks], bh);
                mma_tf32(Sl[nf], qhi[ks], bl);
            }
        }

        float S[4][4];
        const bool needmask = (jt + 31 > ibase + OFF);
#pragma unroll
        for (int nf = 0; nf < 4; nf++)
#pragma unroll
            for (int e = 0; e < 4; e++) {
                float sv = Sh[nf][e] + Sl[nf][e];
                if (needmask) {
                    int row = ibase + g + ((e >= 2) ? 8 : 0);
                    int col = jt + nf * 8 + 2 * c + (e & 1);
                    if (col > row + OFF) sv = -3.0e38f;
                }
                S[nf][e] = sv;
            }

        float mx0 = S[0][0], mx1 = S[0][2];
#pragma unroll
        for (int nf = 0; nf < 4; nf++) {
            mx0 = fmaxf(mx0, fmaxf(S[nf][0], S[nf][1]));
            mx1 = fmaxf(mx1, fmaxf(S[nf][2], S[nf][3]));
        }
        mx0 = fmaxf(mx0, __shfl_xor_sync(0xffffffffu, mx0, 1));
        mx0 = fmaxf(mx0, __shfl_xor_sync(0xffffffffu, mx0, 2));
        mx1 = fmaxf(mx1, __shfl_xor_sync(0xffffffffu, mx1, 1));
        mx1 = fmaxf(mx1, __shfl_xor_sync(0xffffffffu, mx1, 2));
        float mn0 = fmaxf(mrow0, mx0);
        float mn1 = fmaxf(mrow1, mx1);
        float cc0 = __expf(mrow0 - mn0);
        float cc1 = __expf(mrow1 - mn1);
        mrow0 = mn0; mrow1 = mn1;

        float P[4][4];
        float ps0 = 0.f, ps1 = 0.f;
#pragma unroll
        for (int nf = 0; nf < 4; nf++) {
            P[nf][0] = __expf(S[nf][0] - mn0);
            P[nf][1] = __expf(S[nf][1] - mn0);
            P[nf][2] = __expf(S[nf][2] - mn1);
            P[nf][3] = __expf(S[nf][3] - mn1);
            ps0 += P[nf][0] + P[nf][1];
            ps1 += P[nf][2] + P[nf][3];
        }
        den0 = den0 * cc0 + ps0;
        den1 = den1 * cc1 + ps1;
#pragma unroll
        for (int nf = 0; nf < 8; nf++) {
            O[nf][0] *= cc0; O[nf][1] *= cc0;
            O[nf][2] *= cc1; O[nf][3] *= cc1;
        }

#pragma unroll
        for (int nf = 0; nf < 4; nf++) {
            *reinterpret_cast<float2*>(Pw + g * PP + nf * 8 + 2 * c) =
                make_float2(P[nf][0], P[nf][1]);
            *reinterpret_cast<float2*>(Pw + (g + 8) * PP + nf * 8 + 2 * c) =
                make_float2(P[nf][2], P[nf][3]);
        }
        __syncwarp();

        const uint32_t* Vhu = reinterpret_cast<const uint32_t*>(Vhi);
        const uint32_t* Vlu = reinterpret_cast<const uint32_t*>(Vlo);
#pragma unroll
        for (int ks2 = 0; ks2 < 4; ks2++) {
            const int k0 = ks2 * 8;
            uint32_t ahi[4], alo[4];
            float pv;
            pv = Pw[g * PP + k0 + c];           ahi[0] = f2tf(pv); alo[0] = f2tf(pv - __uint_as_float(ahi[0]));
            pv = Pw[(g + 8) * PP + k0 + c];     ahi[1] = f2tf(pv); alo[1] = f2tf(pv - __uint_as_float(ahi[1]));
            pv = Pw[g * PP + k0 + c + 4];       ahi[2] = f2tf(pv); alo[2] = f2tf(pv - __uint_as_float(ahi[2]));
            pv = Pw[(g + 8) * PP + k0 + c + 4]; ahi[3] = f2tf(pv); alo[3] = f2tf(pv - __uint_as_float(ahi[3]));
#pragma unroll
            for (int nf = 0; nf < 8; nf++) {
                const int nn = nf * 8 + g;
                uint32_t bh[2], bl[2];
                bh[0] = Vhu[(k0 + c) * VP + nn];
                bh[1] = Vhu[(k0 + c + 4) * VP + nn];
                bl[0] = Vlu[(k0 + c) * VP + nn];
                bl[1] = Vlu[(k0 + c + 4) * VP + nn];
                mma_tf32(O[nf], ahi, bh);
                mma_tf32(O[nf], alo, bh);
                mma_tf32(O[nf], ahi, bl);
            }
        }
        __syncwarp();
    }

    den0 += __shfl_xor_sync(0xffffffffu, den0, 1);
    den0 += __shfl_xor_sync(0xffffffffu, den0, 2);
    den1 += __shfl_xor_sync(0xffffffffu, den1, 1);
    den1 += __shfl_xor_sync(0xffffffffu, den1, 2);
    float r0 = 1.f / den0, r1 = 1.f / den1;
#pragma unroll
    for (int nf = 0; nf < 8; nf++) {
        int col = hbase + nf * 8 + 2 * c;
        float2 o0 = make_float2(rnd_tf32(O[nf][0] * r0), rnd_tf32(O[nf][1] * r0));
        float2 o1 = make_float2(rnd_tf32(O[nf][2] * r1), rnd_tf32(O[nf][3] * r1));
        *reinterpret_cast<float2*>(out + (size_t)(ibase + g) * INNER + col)     = o0;
        *reinterpret_cast<float2*>(out + (size_t)(ibase + g + 8) * INNER + col) = o1;
    }
}

// ---------------------------------------------------------------------------
// Host orchestration
// ---------------------------------------------------------------------------
static const int SMEM128 = (STAGES * (128 * 36 + BK * 136)) * 4; // 107520 B
static const int SMEM64  = (STAGES * ( 64 * 36 + BK * 136)) * 4; //  79872 B

static void run_sgemm(int epi, const float* A, const float* B, float* C,
                      const float* bias, const float* res, int M, int Nn, int K)
{
    int g128 = (Nn / 128) * (M / 128);
    if (g128 <= 64) {
        dim3 grid(Nn / 128, M / 64);
        switch (epi) {
            case 0: sgemm_kernel<64,0><<<grid, 256, SMEM64>>>(A, B, C, bias, res, M, Nn, K); break;
            case 1: sgemm_kernel<64,1><<<grid, 256, SMEM64>>>(A, B, C, bias, res, M, Nn, K); break;
            case 2: sgemm_kernel<64,2><<<grid, 256, SMEM64>>>(A, B, C, bias, res, M, Nn, K); break;
            case 3: sgemm_kernel<64,3><<<grid, 256, SMEM64>>>(A, B, C, bias, res, M, Nn, K); break;
        }
    } else {
        dim3 grid(Nn / 128, M / 128);
        switch (epi) {
            case 0: sgemm_kernel<128,0><<<grid, 256, SMEM128>>>(A, B, C, bias, res, M, Nn, K); break;
            case 1: sgemm_kernel<128,1><<<grid, 256, SMEM128>>>(A, B, C, bias, res, M, Nn, K); break;
            case 2: sgemm_kernel<128,2><<<grid, 256, SMEM128>>>(A, B, C, bias, res, M, Nn, K); break;
            case 3: sgemm_kernel<128,3><<<grid, 256, SMEM128>>>(A, B, C, bias, res, M, Nn, K); break;
        }
    }
}

extern "C" void kernel_launch(void* const* d_in, const int* in_sizes, int n_in,
                              void* d_out, int out_size)
{
    (void)in_sizes; (void)n_in; (void)out_size;

    const int*   x        = (const int*)  d_in[0];
    const float* tok_emb  = (const float*)d_in[1];
    const float* pos_emb  = (const float*)d_in[2];
    const float* ca_ln_g  = (const float*)d_in[3];
    const float* ca_ln_b  = (const float*)d_in[4];
    const float* ca_wq    = (const float*)d_in[5];
    const float* ca_wkv   = (const float*)d_in[6];
    const float* ca_wo    = (const float*)d_in[7];
    const float* ca_bo    = (const float*)d_in[8];
    const float* cf_ln_g  = (const float*)d_in[9];
    const float* cf_ln_b  = (const float*)d_in[10];
    const float* cf_w1    = (const float*)d_in[11];
    const float* cf_w2    = (const float*)d_in[12];
    const float* la_ln_g  = (const float*)d_in[13];
    const float* la_ln_b  = (const float*)d_in[14];
    const float* la_wqkv  = (const float*)d_in[15];
    const float* la_wo    = (const float*)d_in[16];
    const float* lf_ln_g  = (const float*)d_in[17];
    const float* lf_ln_b  = (const float*)d_in[18];
    const float* lf_w1    = (const float*)d_in[19];
    const float* lf_w2    = (const float*)d_in[20];
    const float* w_logits = (const float*)d_in[21];
    float* out = (float*)d_out;

    cudaFuncSetAttribute(sgemm_kernel<128,0>, cudaFuncAttributeMaxDynamicSharedMemorySize, SMEM128);
    cudaFuncSetAttribute(sgemm_kernel<128,1>, cudaFuncAttributeMaxDynamicSharedMemorySize, SMEM128);
    cudaFuncSetAttribute(sgemm_kernel<128,2>, cudaFuncAttributeMaxDynamicSharedMemorySize, SMEM128);
    cudaFuncSetAttribute(sgemm_kernel<128,3>, cudaFuncAttributeMaxDynamicSharedMemorySize, SMEM128);
    cudaFuncSetAttribute(sgemm_kernel<64,0>,  cudaFuncAttributeMaxDynamicSharedMemorySize, SMEM64);
    cudaFuncSetAttribute(sgemm_kernel<64,1>,  cudaFuncAttributeMaxDynamicSharedMemorySize, SMEM64);
    cudaFuncSetAttribute(sgemm_kernel<64,2>,  cudaFuncAttributeMaxDynamicSharedMemorySize, SMEM64);
    cudaFuncSetAttribute(sgemm_kernel<64,3>,  cudaFuncAttributeMaxDynamicSharedMemorySize, SMEM64);
    cudaFuncSetAttribute(attn_kernel<0>, cudaFuncAttributeMaxDynamicSharedMemorySize, ATT_SMEM);
    cudaFuncSetAttribute(attn_kernel<1>, cudaFuncAttributeMaxDynamicSharedMemorySize, ATT_SMEM);

    // Side stream + fork/join events, created once on the first (uncaptured)
    // correctness call; reused identically on every subsequent call.
    static cudaStream_t s_side = nullptr;
    static cudaEvent_t  ev_fork = nullptr, ev_join = nullptr;
    if (s_side == nullptr) {
        cudaStreamCreateWithFlags(&s_side, cudaStreamNonBlocking);
        cudaEventCreateWithFlags(&ev_fork, cudaEventDisableTiming);
        cudaEventCreateWithFlags(&ev_join, cudaEventDisableTiming);
    }

    float *prefix, *h, *xn, *kvctx, *attn, *ff, *qkv, *w;
    cudaGetSymbolAddress((void**)&prefix, g_prefix);
    cudaGetSymbolAddress((void**)&h,      g_h);
    cudaGetSymbolAddress((void**)&xn,     g_xn);
    cudaGetSymbolAddress((void**)&kvctx,  g_kvctx);
    cudaGetSymbolAddress((void**)&attn,   g_attn);
    cudaGetSymbolAddress((void**)&ff,     g_ff);
    cudaGetSymbolAddress((void**)&qkv,    g_qkv);
    cudaGetSymbolAddress((void**)&w,      g_w);

    // 0a. FORK: deferred weight rounding on side stream (latent + logits
    //     weights, ~83M floats). Hidden under the cross block.
    cudaEventRecord(ev_fork, 0);
    cudaStreamWaitEvent(s_side, ev_fork, 0);
    {
        // block counts (floats/4096): LQKV 3072, LWO 1024, LF1 4096, LF2 4096, LOG 8000
        int e0 = 3072, e1 = 4096, e2 = 8192, e3 = 12288;
        int grid = 20288;
        round_multi_kernel<<<grid, 256, 0, s_side>>>(
            la_wqkv, la_wo, lf_w1, lf_w2, w_logits, w + W_LQKV, e0, e1, e2, e3);
    }
    cudaEventRecord(ev_join, s_side);

    // 0b. Early weights on main stream (needed by the cross block).
    {
        int n4 = (DMODEL * 3 * INNER) / 4;
        pack_cqkv_kernel<<<(n4 + 255) / 256, 256>>>(ca_wq, ca_wkv, w + W_CQKV);
    }
    {
        // WKV 512, WO 256, CF1 1024, CF2 1024 -> grid 2816 (4 segments; s4 dummy)
        int e0 = 512, e1 = 768, e2 = 1792, e3 = 2816;
        round_multi_kernel<<<2816, 256>>>(
            ca_wkv, ca_wo, cf_w1, cf_w2, cf_w2, w + W_WKV, e0, e1, e2, e3);
    }

    // 1. Embedding
    embed_kernel<<<(NCTX * DMODEL) / 256, 256>>>(x, tok_emb, pos_emb);

    // 2. Cross-attention block (fused qkv projection)
    ln_kernel<<<LAT, 256>>>(h, xn, ca_ln_g, ca_ln_b);
    run_sgemm(0, xn,     w + W_CQKV, qkv,   nullptr, nullptr, LAT, 3 * INNER, DMODEL);
    run_sgemm(0, prefix, w + W_WKV,  kvctx, nullptr, nullptr, PFX, 2 * INNER, DMODEL);
    {
        dim3 gg(LAT / 64, NHEAD);
        attn_kernel<1><<<gg, 128, ATT_SMEM>>>(qkv, kvctx, attn);
    }
    run_sgemm(1, attn, w + W_WO, h, ca_bo, h, LAT, DMODEL, INNER);

    // 3. Cross FFN
    ln_kernel<<<LAT, 256>>>(h, xn, cf_ln_g, cf_ln_b);
    run_sgemm(3, xn, w + W_CF1, ff, nullptr, nullptr, LAT, FFDIM, DMODEL);
    run_sgemm(2, ff, w + W_CF2, h, nullptr, h, LAT, DMODEL, FFDIM);

    // JOIN: latent/logits weights must be rounded from here on.
    cudaStreamWaitEvent(0, ev_join, 0);

    // 4. Latent self-attention layers
    for (int l = 0; l < DEPTH; l++) {
        ln_kernel<<<LAT, 256>>>(h, xn, la_ln_g + (size_t)l * DMODEL, la_ln_b + (size_t)l * DMODEL);
        run_sgemm(0, xn, w + W_LQKV + (size_t)l * DMODEL * 3 * INNER, qkv,
                  nullptr, nullptr, LAT, 3 * INNER, DMODEL);
        {
            dim3 gg(LAT / 64, NHEAD);
            attn_kernel<0><<<gg, 128, ATT_SMEM>>>(qkv, nullptr, attn);
        }
        run_sgemm(2, attn, w + W_LWO + (size_t)l * INNER * DMODEL, h, nullptr, h, LAT, DMODEL, INNER);

        ln_kernel<<<LAT, 256>>>(h, xn, lf_ln_g + (size_t)l * DMODEL, lf_ln_b + (size_t)l * DMODEL);
        run_sgemm(3, xn, w + W_LF1 + (size_t)l * DMODEL * FFDIM, ff, nullptr, nullptr, LAT, FFDIM, DMODEL);
        run_sgemm(2, ff, w + W_LF2 + (size_t)l * FFDIM * DMODEL, h, nullptr, h, LAT, DMODEL, FFDIM);
    }

    // 5. Logits (round h into xn first: h itself must stay fp32)
    round_kernel<<<(LAT * DMODEL / 4) / 1024, 256>>>(h, xn, LAT * DMODEL / 4);
    run_sgemm(0, xn, w + W_LOG, out, nullptr, nullptr, LAT, VOCAB, DMODEL);
}

// round 16
// speedup vs baseline: 1.5268x; 1.5268x over previous
#include <cuda_runtime.h>
#include <cuda_bf16.h>
#include <math.h>
#include <stdint.h>

// Problem constants
#define NCTX   4096
#define DMODEL 1024
#define NHEAD  16
#define DHEAD  64
#define DEPTH  4
#define PFX    3072
#define LAT    1024          // NCTX - PFX
#define FFDIM  4096
#define VOCAB  32000
#define INNER  1024          // NHEAD * DHEAD

// ---------------------------------------------------------------------------
// Scratch (static __device__ globals; no runtime allocation)
// ---------------------------------------------------------------------------
__device__ float g_prefix[PFX * DMODEL];
__device__ float g_h     [LAT * DMODEL];
__device__ float g_xn    [LAT * DMODEL];
__device__ float g_kvctx [PFX * 2 * INNER];
__device__ float g_attn  [LAT * INNER];
__device__ float g_ff    [LAT * FFDIM];
__device__ float g_qkv   [LAT * 3 * INNER];

// tf32-rounded weight scratch (one big buffer, float offsets)
#define W_CQKV  0
#define W_WKV   (W_CQKV + DMODEL * 3 * INNER)
#define W_WO    (W_WKV  + DMODEL * 2 * INNER)
#define W_CF1   (W_WO   + INNER * DMODEL)
#define W_CF2   (W_CF1  + DMODEL * FFDIM)
#define W_LQKV  (W_CF2  + FFDIM * DMODEL)
#define W_LWO   (W_LQKV + DEPTH * DMODEL * 3 * INNER)
#define W_LF1   (W_LWO  + DEPTH * INNER * DMODEL)
#define W_LF2   (W_LF1  + DEPTH * DMODEL * FFDIM)
#define W_LOG   (W_LF2  + DEPTH * FFDIM * DMODEL)
#define W_TOTAL (W_LOG  + DMODEL * VOCAB)
__device__ float g_w[W_TOTAL];

// ---------------------------------------------------------------------------
// tf32 rounding helpers
// ---------------------------------------------------------------------------
__device__ __forceinline__ uint32_t f2tf(float x) {
    uint32_t r;
    asm("cvt.rna.tf32.f32 %0, %1;" : "=r"(r) : "f"(x));
    return r;
}
__device__ __forceinline__ float rnd_tf32(float x) {
    return __uint_as_float(f2tf(x));
}

// ---------------------------------------------------------------------------
// Fused multi-segment tf32 rounding. Each block rounds 4096 floats
// (256 thr x 4 float4, MLP=4). Segments are contiguous in dst; block-prefix
// ends e0..e3 select the source. All segment sizes are multiples of 4096.
// ---------------------------------------------------------------------------
__global__ void round_multi_kernel(
    const float* __restrict__ s0, const float* __restrict__ s1,
    const float* __restrict__ s2, const float* __restrict__ s3,
    const float* __restrict__ s4, float* __restrict__ dst,
    int e0, int e1, int e2, int e3)
{
    int b = blockIdx.x;
    const float* src; int rel;
    if      (b < e0) { src = s0; rel = b; }
    else if (b < e1) { src = s1; rel = b - e0; }
    else if (b < e2) { src = s2; rel = b - e1; }
    else if (b < e3) { src = s3; rel = b - e2; }
    else             { src = s4; rel = b - e3; }
    const float4* s4p = reinterpret_cast<const float4*>(src) + (size_t)rel * 1024;
    float4* d4p = reinterpret_cast<float4*>(dst) + (size_t)b * 1024;
    int t = threadIdx.x;
    float4 v[4];
#pragma unroll
    for (int u = 0; u < 4; u++) v[u] = s4p[t + u * 256];
#pragma unroll
    for (int u = 0; u < 4; u++) {
        v[u].x = rnd_tf32(v[u].x); v[u].y = rnd_tf32(v[u].y);
        v[u].z = rnd_tf32(v[u].z); v[u].w = rnd_tf32(v[u].w);
        d4p[t + u * 256] = v[u];
    }
}

// Single-array rounding (used for h -> xn before logits)
__global__ void round_kernel(const float* __restrict__ in,
                             float* __restrict__ out, int n4)
{
    int i0 = blockIdx.x * 1024 + threadIdx.x;
    float4 v[4];
#pragma unroll
    for (int u = 0; u < 4; u++)
        v[u] = reinterpret_cast<const float4*>(in)[i0 + u * 256];
#pragma unroll
    for (int u = 0; u < 4; u++) {
        v[u].x = rnd_tf32(v[u].x); v[u].y = rnd_tf32(v[u].y);
        v[u].z = rnd_tf32(v[u].z); v[u].w = rnd_tf32(v[u].w);
        reinterpret_cast<float4*>(out)[i0 + u * 256] = v[u];
    }
}

// Pack [wq | wkv] -> row-major [DMODEL][3*INNER], tf32-rounded.
__global__ void pack_cqkv_kernel(const float* __restrict__ wq,
                                 const float* __restrict__ wkv,
                                 float* __restrict__ dst)
{
    int i = blockIdx.x * blockDim.x + threadIdx.x;  // over D*3I/4
    if (i >= (DMODEL * 3 * INNER) / 4) return;
    int i4 = i * 4;
    int d = i4 / (3 * INNER);
    int j = i4 % (3 * INNER);
    float4 v;
    if (j < INNER)
        v = *reinterpret_cast<const float4*>(wq + (size_t)d * INNER + j);
    else
        v = *reinterpret_cast<const float4*>(wkv + (size_t)d * 2 * INNER + (j - INNER));
    v.x = rnd_tf32(v.x); v.y = rnd_tf32(v.y);
    v.z = rnd_tf32(v.z); v.w = rnd_tf32(v.w);
    reinterpret_cast<float4*>(dst)[i] = v;
}

// ---------------------------------------------------------------------------
// Embedding, float4-vectorized (4 elems/thread).
// prefix feeds GEMM only -> pre-rounded; h stays fp32.
// ---------------------------------------------------------------------------
__global__ void embed_kernel(const int* __restrict__ x,
                             const float* __restrict__ tok,
                             const float* __restrict__ pos)
{
    int i = blockIdx.x * blockDim.x + threadIdx.x;   // over NCTX*DMODEL/4
    int n = i >> 8;             // / 256 (=1024/4)
    int d4 = i & 255;
    float4 t4 = *(reinterpret_cast<const float4*>(tok + (size_t)x[n] * DMODEL) + d4);
    float4 p4 = reinterpret_cast<const float4*>(pos)[i];
    t4.x += p4.x; t4.y += p4.y; t4.z += p4.z; t4.w += p4.w;
    if (n < PFX) {
        t4.x = rnd_tf32(t4.x); t4.y = rnd_tf32(t4.y);
        t4.z = rnd_tf32(t4.z); t4.w = rnd_tf32(t4.w);
        reinterpret_cast<float4*>(g_prefix)[i] = t4;
    } else {
        reinterpret_cast<float4*>(g_h)[i - PFX * 256] = t4;
    }
}

// ---------------------------------------------------------------------------
// LayerNorm (D=1024); output feeds GEMM A only -> pre-rounded to tf32
// ---------------------------------------------------------------------------
__global__ __launch_bounds__(256) void ln_kernel(
    const float* __restrict__ in, float* __restrict__ out,
    const float* __restrict__ g, const float* __restrict__ b)
{
    int row = blockIdx.x;
    const float* p = in + (size_t)row * DMODEL;
    float vals[4];
    float s = 0.f, s2 = 0.f;
#pragma unroll
    for (int u = 0; u < 4; u++) {
        float v = p[threadIdx.x + u * 256];
        vals[u] = v; s += v; s2 += v * v;
    }
#pragma unroll
    for (int o = 16; o; o >>= 1) {
        s  += __shfl_xor_sync(0xffffffffu, s,  o);
        s2 += __shfl_xor_sync(0xffffffffu, s2, o);
    }
    __shared__ float sh[2][8];
    int wid = threadIdx.x >> 5, lane = threadIdx.x & 31;
    if (lane == 0) { sh[0][wid] = s; sh[1][wid] = s2; }
    __syncthreads();
    s = 0.f; s2 = 0.f;
#pragma unroll
    for (int w = 0; w < 8; w++) { s += sh[0][w]; s2 += sh[1][w]; }
    float mean = s * (1.f / DMODEL);
    float var  = s2 * (1.f / DMODEL) - mean * mean;
    float inv  = rsqrtf(var + 1e-5f);
#pragma unroll
    for (int u = 0; u < 4; u++) {
        int d = threadIdx.x + u * 256;
        out[(size_t)row * DMODEL + d] =
            rnd_tf32((vals[u] - mean) * inv * g[d] + b[d]);
    }
}

// ---------------------------------------------------------------------------
// TF32 tensor-core GEMM with cp.async 3-stage pipeline, BK=32 (R14 proven).
// ---------------------------------------------------------------------------
#define BK 32
#define STAGES 3

__device__ __forceinline__ uint32_t smem_u32(const void* p) {
    return static_cast<uint32_t>(__cvta_generic_to_shared(p));
}

__device__ __forceinline__ void mma_tf32(float* d, const uint32_t* a, const uint32_t* b) {
    asm volatile(
        "mma.sync.aligned.m16n8k8.row.col.f32.tf32.tf32.f32 "
        "{%0,%1,%2,%3}, {%4,%5,%6,%7}, {%8,%9}, {%0,%1,%2,%3};"
        : "+f"(d[0]), "+f"(d[1]), "+f"(d[2]), "+f"(d[3])
        : "r"(a[0]), "r"(a[1]), "r"(a[2]), "r"(a[3]), "r"(b[0]), "r"(b[1]));
}

template <int BM, int EPI>
__global__ __launch_bounds__(256, 2) void sgemm_kernel(
    const float* __restrict__ A, const float* __restrict__ B,
    float* __restrict__ C, const float* __restrict__ bias,
    const float* __restrict__ res, int M, int Nn, int K)
{
    constexpr int MF = BM / 32;
    constexpr int AP = BK + 4;    // 36
    constexpr int BP = 136;
    extern __shared__ __align__(16) float smem[];
    float* As = smem;                          // [STAGES][BM][AP]
    float* Bs = smem + STAGES * BM * AP;       // [STAGES][BK][BP]

    const int tid  = threadIdx.x;
    const int lane = tid & 31, wid = tid >> 5;
    const int g = lane >> 2, c = lane & 3;
    const int wm = (wid & 1) * (BM / 2);
    const int wn = (wid >> 1) * 32;
    const int bx = blockIdx.x, by = blockIdx.y;

    const int nt = K / BK;

    auto issue_stage = [&](int kt, int slot) {
        const float* Ag = A + (size_t)(by * BM) * K + kt * BK;
#pragma unroll
        for (int r = 0; r < BM / 32; r++) {
            int ch = tid + r * 256;
            int m = ch >> 3, ko = (ch & 7) << 2;
            uint32_t dst = smem_u32(&As[(slot * BM + m) * AP + ko]);
            const float* src = Ag + (size_t)m * K + ko;
            asm volatile("cp.async.cg.shared.global [%0], [%1], 16;"
                         :: "r"(dst), "l"(src) : "memory");
        }
        const float* Bg = B + (size_t)(kt * BK) * Nn + bx * 128;
#pragma unroll
        for (int r = 0; r < 4; r++) {
            int ch = tid + r * 256;
            int kr = ch >> 5, no = (ch & 31) << 2;
            uint32_t dst = smem_u32(&Bs[(slot * BK + kr) * BP + no]);
            const float* src = Bg + (size_t)kr * Nn + no;
            asm volatile("cp.async.cg.shared.global [%0], [%1], 16;"
                         :: "r"(dst), "l"(src) : "memory");
        }
        asm volatile("cp.async.commit_group;" ::: "memory");
    };

    float acc[MF][4][4];
#pragma unroll
    for (int mf = 0; mf < MF; mf++)
#pragma unroll
        for (int nf = 0; nf < 4; nf++)
#pragma unroll
            for (int i = 0; i < 4; i++) acc[mf][nf][i] = 0.f;

#pragma unroll
    for (int s = 0; s < STAGES - 1; s++) issue_stage(s, s);

    for (int kt = 0; kt < nt; kt++) {
        asm volatile("cp.async.wait_group %0;" :: "n"(STAGES - 2) : "memory");
        __syncthreads();
        if (kt + STAGES - 1 < nt)
            issue_stage(kt + STAGES - 1, (kt + STAGES - 1) % STAGES);
        else
            asm volatile("cp.async.commit_group;" ::: "memory");

        const int slot = kt % STAGES;
        const uint32_t* Asl = reinterpret_cast<const uint32_t*>(&As[slot * BM * AP]);
        const uint32_t* Bsl = reinterpret_cast<const uint32_t*>(&Bs[slot * BK * BP]);

#pragma unroll
        for (int ks = 0; ks < 4; ks++) {
            const int k0 = ks * 8;
            uint32_t af[MF][4], bf[4][2];
#pragma unroll
            for (int mf = 0; mf < MF; mf++) {
                const int mrow = wm + mf * 16 + g;
                af[mf][0] = Asl[(size_t)mrow * AP + k0 + c];
                af[mf][1] = Asl[(size_t)(mrow + 8) * AP + k0 + c];
                af[mf][2] = Asl[(size_t)mrow * AP + k0 + c + 4];
                af[mf][3] = Asl[(size_t)(mrow + 8) * AP + k0 + c + 4];
            }
#pragma unroll
            for (int nf = 0; nf < 4; nf++) {
                const int ncol = wn + nf * 8 + g;
                bf[nf][0] = Bsl[(size_t)(k0 + c) * BP + ncol];
                bf[nf][1] = Bsl[(size_t)(k0 + c + 4) * BP + ncol];
            }
#pragma unroll
            for (int mf = 0; mf < MF; mf++)
#pragma unroll
                for (int nf = 0; nf < 4; nf++)
                    mma_tf32(acc[mf][nf], af[mf], bf[nf]);
        }
    }

#pragma unroll
    for (int mf = 0; mf < MF; mf++) {
#pragma unroll
        for (int nf = 0; nf < 4; nf++) {
            int row = by * BM + wm + mf * 16 + g;
            int col = bx * 128 + wn + nf * 8 + 2 * c;
#pragma unroll
            for (int half = 0; half < 2; half++) {
                int r = row + half * 8;
                float v0 = acc[mf][nf][half * 2 + 0];
                float v1 = acc[mf][nf][half * 2 + 1];
                if (EPI == 1) {
                    v0 += bias[col]     + res[(size_t)r * Nn + col];
                    v1 += bias[col + 1] + res[(size_t)r * Nn + col + 1];
                }
                if (EPI == 2) {
                    v0 += res[(size_t)r * Nn + col];
                    v1 += res[(size_t)r * Nn + col + 1];
                }
                if (EPI == 3) {
                    v0 = 0.5f * v0 * (1.f + erff(v0 * 0.70710678f));
                    v1 = 0.5f * v1 * (1.f + erff(v1 * 0.70710678f));
                    v0 = rnd_tf32(v0);
                    v1 = rnd_tf32(v1);
                }
                float2 o = make_float2(v0, v1);
                *reinterpret_cast<float2*>(C + (size_t)r * Nn + col) = o;
            }
        }
    }
}

// ---------------------------------------------------------------------------
// Tensor-core attention with split-tf32 (unchanged from passing R11/R14).
// ---------------------------------------------------------------------------
#define QP 68
#define KP 40
#define VP 72
#define PP 40
#define ATT_SMEM ((64*QP + 2*64*KP + 2*32*VP + 4*16*PP) * 4)

template <int CROSS>
__global__ __launch_bounds__(128) void attn_kernel(
    const float* __restrict__ qsrc, const float* __restrict__ kvctx,
    float* __restrict__ out)
{
    const int OFF = CROSS ? PFX : 0;
    const int hbase = blockIdx.y * DHEAD;
    const int qbase = blockIdx.x * 64;
    const int wid = threadIdx.x >> 5, lane = threadIdx.x & 31;
    const int g = lane >> 2, c = lane & 3;
    const int ibase = qbase + wid * 16;

    extern __shared__ __align__(16) float sm[];
    float* Qs   = sm;
    float* KThi = Qs   + 64 * QP;
    float* KTlo = KThi + 64 * KP;
    float* Vhi  = KTlo + 64 * KP;
    float* Vlo  = Vhi  + 32 * VP;
    float* Ps   = Vlo  + 32 * VP;

    {
        int qr = threadIdx.x >> 1;
        int half = (threadIdx.x & 1) * 32;
        const float* qp = qsrc + (size_t)(qbase + qr) * 3072 + hbase + half;
        float* dst = Qs + qr * QP + half;
#pragma unroll
        for (int u = 0; u < 8; u++) {
            float4 v = *reinterpret_cast<const float4*>(qp + u * 4);
            dst[u * 4 + 0] = v.x * 0.125f;
            dst[u * 4 + 1] = v.y * 0.125f;
            dst[u * 4 + 2] = v.z * 0.125f;
            dst[u * 4 + 3] = v.w * 0.125f;
        }
    }
    __syncthreads();

    uint32_t qhi[8][4], qlo[8][4];
#pragma unroll
    for (int ks = 0; ks < 8; ks++) {
        const int k0 = ks * 8;
        const int r0 = (wid * 16 + g) * QP, r1 = (wid * 16 + g + 8) * QP;
        float v;
        v = Qs[r0 + k0 + c];     qhi[ks][0] = f2tf(v); qlo[ks][0] = f2tf(v - __uint_as_float(qhi[ks][0]));
        v = Qs[r1 + k0 + c];     qhi[ks][1] = f2tf(v); qlo[ks][1] = f2tf(v - __uint_as_float(qhi[ks][1]));
        v = Qs[r0 + k0 + c + 4]; qhi[ks][2] = f2tf(v); qlo[ks][2] = f2tf(v - __uint_as_float(qhi[ks][2]));
        v = Qs[r1 + k0 + c + 4]; qhi[ks][3] = f2tf(v); qlo[ks][3] = f2tf(v - __uint_as_float(qhi[ks][3]));
    }

    float O[8][4];
#pragma unroll
    for (int nf = 0; nf < 8; nf++)
#pragma unroll
        for (int e = 0; e < 4; e++) O[nf][e] = 0.f;
    float mrow0 = -3.0e38f, mrow1 = -3.0e38f;
    float den0 = 0.f, den1 = 0.f;

    const int ntiles = (qbase + 64 + OFF) / 32;
    float* Pw = Ps + wid * 16 * PP;

    for (int t = 0; t < ntiles; t++) {
        const int jt = t * 32;
        __syncthreads();
        {
            int key = threadIdx.x >> 2;
            int d0  = (threadIdx.x & 3) * 16;
            int j = jt + key;
            const float *kp, *vp;
            if (CROSS && j < PFX) {
                kp = kvctx + (size_t)j * 2048 + hbase;
                vp = kp + INNER;
            } else {
                int jj = CROSS ? j - PFX : j;
                if (jj > LAT - 1) jj = LAT - 1;
                kp = qsrc + (size_t)jj * 3072 + INNER + hbase;
                vp = kp + INNER;
            }
#pragma unroll
            for (int u = 0; u < 4; u++) {
                float4 k4 = *reinterpret_cast<const float4*>(kp + d0 + u * 4);
                float4 v4 = *reinterpret_cast<const float4*>(vp + d0 + u * 4);
                const float ke[4] = {k4.x, k4.y, k4.z, k4.w};
                float4 vh, vl;
                float* vhp = &vh.x; float* vlp = &vl.x;
                const float ve[4] = {v4.x, v4.y, v4.z, v4.w};
#pragma unroll
                for (int e = 0; e < 4; e++) {
                    int d = d0 + u * 4 + e;
                    float khi = rnd_tf32(ke[e]);
                    KThi[d * KP + key] = khi;
                    KTlo[d * KP + key] = rnd_tf32(ke[e] - khi);
                    float vhi = rnd_tf32(ve[e]);
                    vhp[e] = vhi;
                    vlp[e] = rnd_tf32(ve[e] - vhi);
                }
                *reinterpret_cast<float4*>(Vhi + key * VP + d0 + u * 4) = vh;
                *reinterpret_cast<float4*>(Vlo + key * VP + d0 + u * 4) = vl;
            }
        }
        __syncthreads();

        if (jt > ibase + 15 + OFF) continue;

        float Sh[4][4], Sl[4][4];
#pragma unroll
        for (int nf = 0; nf < 4; nf++)
#pragma unroll
            for (int e = 0; e < 4; e++) { Sh[nf][e] = 0.f; Sl[nf][e] = 0.f; }
        const uint32_t* KThu = reinterpret_cast<const uint32_t*>(KThi);
        const uint32_t* KTlu = reinterpret_cast<const uint32_t*>(KTlo);
#pragma unroll
        for (int nf = 0; nf < 4; nf++) {
            const int nn = nf * 8 + g;
#pragma unroll
            for (int ks = 0; ks < 8; ks++) {
                const int k0 = ks * 8;
                uint32_t bh[2], bl[2];
                bh[0] = KThu[(k0 + c) * KP + nn];
                bh[1] = KThu[(k0 + c + 4) * KP + nn];
                bl[0] = KTlu[(k0 + c) * KP + nn];
                bl[1] = KTlu[(k0 + c + 4) * KP + nn];
                mma_tf32(Sh[nf], qhi[ks], bh);
                mma_tf32(Sl[nf], qlo[ks], bh);
                mma_tf32(Sl[nf], qhi[ks], bl);
            }
        }

        float S[4][4];
        const bool needmask = (jt + 31 > ibase + OFF);
#pragma unroll
        for (int nf = 0; nf < 4; nf++)
#pragma unroll
            for (int e = 0; e < 4; e++) {
                float sv = Sh[nf][e] + Sl[nf][e];
                if (needmask) {
                    int row = ibase + g + ((e >= 2) ? 8 : 0);
                    int col = jt + nf * 8 + 2 * c + (e & 1);
                    if (col > row + OFF) sv = -3.0e38f;
                }
                S[nf][e] = sv;
            }

        float mx0 = S[0][0], mx1 = S[0][2];
#pragma unroll
        for (int nf = 0; nf < 4; nf++) {
            mx0 = fmaxf(mx0, fmaxf(S[nf][0], S[nf][1]));
            mx1 = fmaxf(mx1, fmaxf(S[nf][2], S[nf][3]));
        }
        mx0 = fmaxf(mx0, __shfl_xor_sync(0xffffffffu, mx0, 1));
        mx0 = fmaxf(mx0, __shfl_xor_sync(0xffffffffu, mx0, 2));
        mx1 = fmaxf(mx1, __shfl_xor_sync(0xffffffffu, mx1, 1));
        mx1 = fmaxf(mx1, __shfl_xor_sync(0xffffffffu, mx1, 2));
        float mn0 = fmaxf(mrow0, mx0);
        float mn1 = fmaxf(mrow1, mx1);
        float cc0 = __expf(mrow0 - mn0);
        float cc1 = __expf(mrow1 - mn1);
        mrow0 = mn0; mrow1 = mn1;

        float P[4][4];
        float ps0 = 0.f, ps1 = 0.f;
#pragma unroll
        for (int nf = 0; nf < 4; nf++) {
            P[nf][0] = __expf(S[nf][0] - mn0);
            P[nf][1] = __expf(S[nf][1] - mn0);
            P[nf][2] = __expf(S[nf][2] - mn1);
            P[nf][3] = __expf(S[nf][3] - mn1);
            ps0 += P[nf][0] + P[nf][1];
            ps1 += P[nf][2] + P[nf][3];
        }
        den0 = den0 * cc0 + ps0;
        den1 = den1 * cc1 + ps1;
#pragma unroll
        for (int nf = 0; nf < 8; nf++) {
            O[nf][0] *= cc0; O[nf][1] *= cc0;
            O[nf][2] *= cc1; O[nf][3] *= cc1;
        }

#pragma unroll
        for (int nf = 0; nf < 4; nf++) {
            *reinterpret_cast<float2*>(Pw + g * PP + nf * 8 + 2 * c) =
                make_float2(P[nf][0], P[nf][1]);
            *reinterpret_cast<float2*>(Pw + (g + 8) * PP + nf * 8 + 2 * c) =
                make_float2(P[nf][2], P[nf][3]);
        }
        __syncwarp();

        const uint32_t* Vhu = reinterpret_cast<const uint32_t*>(Vhi);
        const uint32_t* Vlu = reinterpret_cast<const uint32_t*>(Vlo);
#pragma unroll
        for (int ks2 = 0; ks2 < 4; ks2++) {
            const int k0 = ks2 * 8;
            uint32_t ahi[4], alo[4];
            float pv;
            pv = Pw[g * PP + k0 + c];           ahi[0] = f2tf(pv); alo[0] = f2tf(pv - __uint_as_float(ahi[0]));
            pv = Pw[(g + 8) * PP + k0 + c];     ahi[1] = f2tf(pv); alo[1] = f2tf(pv - __uint_as_float(ahi[1]));
            pv = Pw[g * PP + k0 + c + 4];       ahi[2] = f2tf(pv); alo[2] = f2tf(pv - __uint_as_float(ahi[2]));
            pv = Pw[(g + 8) * PP + k0 + c + 4]; ahi[3] = f2tf(pv); alo[3] = f2tf(pv - __uint_as_float(ahi[3]));
#pragma unroll
            for (int nf = 0; nf < 8; nf++) {
                const int nn = nf * 8 + g;
                uint32_t bh[2], bl[2];
                bh[0] = Vhu[(k0 + c) * VP + nn];
                bh[1] = Vhu[(k0 + c + 4) * VP + nn];
                bl[0] = Vlu[(k0 + c) * VP + nn];
                bl[1] = Vlu[(k0 + c + 4) * VP + nn];
                mma_tf32(O[nf], ahi, bh);
                mma_tf32(O[nf], alo, bh);
                mma_tf32(O[nf], ahi, bl);
            }
        }
        __syncwarp();
    }

    den0 += __shfl_xor_sync(0xffffffffu, den0, 1);
    den0 += __shfl_xor_sync(0xffffffffu, den0, 2);
    den1 += __shfl_xor_sync(0xffffffffu, den1, 1);
    den1 += __shfl_xor_sync(0xffffffffu, den1, 2);
    float r0 = 1.f / den0, r1 = 1.f / den1;
#pragma unroll
    for (int nf = 0; nf < 8; nf++) {
        int col = hbase + nf * 8 + 2 * c;
        float2 o0 = make_float2(rnd_tf32(O[nf][0] * r0), rnd_tf32(O[nf][1] * r0));
        float2 o1 = make_float2(rnd_tf32(O[nf][2] * r1), rnd_tf32(O[nf][3] * r1));
        *reinterpret_cast<float2*>(out + (size_t)(ibase + g) * INNER + col)     = o0;
        *reinterpret_cast<float2*>(out + (size_t)(ibase + g + 8) * INNER + col) = o1;
    }
}

// ---------------------------------------------------------------------------
// Host orchestration (single stream — R14 structure)
// ---------------------------------------------------------------------------
static const int SMEM128 = (STAGES * (128 * 36 + BK * 136)) * 4; // 107520 B
static const int SMEM64  = (STAGES * ( 64 * 36 + BK * 136)) * 4; //  79872 B

static void run_sgemm(int epi, const float* A, const float* B, float* C,
                      const float* bias, const float* res, int M, int Nn, int K)
{
    int g128 = (Nn / 128) * (M / 128);
    if (g128 <= 64) {
        dim3 grid(Nn / 128, M / 64);
        switch (epi) {
            case 0: sgemm_kernel<64,0><<<grid, 256, SMEM64>>>(A, B, C, bias, res, M, Nn, K); break;
            case 1: sgemm_kernel<64,1><<<grid, 256, SMEM64>>>(A, B, C, bias, res, M, Nn, K); break;
            case 2: sgemm_kernel<64,2><<<grid, 256, SMEM64>>>(A, B, C, bias, res, M, Nn, K); break;
            case 3: sgemm_kernel<64,3><<<grid, 256, SMEM64>>>(A, B, C, bias, res, M, Nn, K); break;
        }
    } else {
        dim3 grid(Nn / 128, M / 128);
        switch (epi) {
            case 0: sgemm_kernel<128,0><<<grid, 256, SMEM128>>>(A, B, C, bias, res, M, Nn, K); break;
            case 1: sgemm_kernel<128,1><<<grid, 256, SMEM128>>>(A, B, C, bias, res, M, Nn, K); break;
            case 2: sgemm_kernel<128,2><<<grid, 256, SMEM128>>>(A, B, C, bias, res, M, Nn, K); break;
            case 3: sgemm_kernel<128,3><<<grid, 256, SMEM128>>>(A, B, C, bias, res, M, Nn, K); break;
        }
    }
}

extern "C" void kernel_launch(void* const* d_in, const int* in_sizes, int n_in,
                              void* d_out, int out_size)
{
    (void)in_sizes; (void)n_in; (void)out_size;

    const int*   x        = (const int*)  d_in[0];
    const float* tok_emb  = (const float*)d_in[1];
    const float* pos_emb  = (const float*)d_in[2];
    const float* ca_ln_g  = (const float*)d_in[3];
    const float* ca_ln_b  = (const float*)d_in[4];
    const float* ca_wq    = (const float*)d_in[5];
    const float* ca_wkv   = (const float*)d_in[6];
    const float* ca_wo    = (const float*)d_in[7];
    const float* ca_bo    = (const float*)d_in[8];
    const float* cf_ln_g  = (const float*)d_in[9];
    const float* cf_ln_b  = (const float*)d_in[10];
    const float* cf_w1    = (const float*)d_in[11];
    const float* cf_w2    = (const float*)d_in[12];
    const float* la_ln_g  = (const float*)d_in[13];
    const float* la_ln_b  = (const float*)d_in[14];
    const float* la_wqkv  = (const float*)d_in[15];
    const float* la_wo    = (const float*)d_in[16];
    const float* lf_ln_g  = (const float*)d_in[17];
    const float* lf_ln_b  = (const float*)d_in[18];
    const float* lf_w1    = (const float*)d_in[19];
    const float* lf_w2    = (const float*)d_in[20];
    const float* w_logits = (const float*)d_in[21];
    float* out = (float*)d_out;

    cudaFuncSetAttribute(sgemm_kernel<128,0>, cudaFuncAttributeMaxDynamicSharedMemorySize, SMEM128);
    cudaFuncSetAttribute(sgemm_kernel<128,1>, cudaFuncAttributeMaxDynamicSharedMemorySize, SMEM128);
    cudaFuncSetAttribute(sgemm_kernel<128,2>, cudaFuncAttributeMaxDynamicSharedMemorySize, SMEM128);
    cudaFuncSetAttribute(sgemm_kernel<128,3>, cudaFuncAttributeMaxDynamicSharedMemorySize, SMEM128);
    cudaFuncSetAttribute(sgemm_kernel<64,0>,  cudaFuncAttributeMaxDynamicSharedMemorySize, SMEM64);
    cudaFuncSetAttribute(sgemm_kernel<64,1>,  cudaFuncAttributeMaxDynamicSharedMemorySize, SMEM64);
    cudaFuncSetAttribute(sgemm_kernel<64,2>,  cudaFuncAttributeMaxDynamicSharedMemorySize, SMEM64);
    cudaFuncSetAttribute(sgemm_kernel<64,3>,  cudaFuncAttributeMaxDynamicSharedMemorySize, SMEM64);
    cudaFuncSetAttribute(attn_kernel<0>, cudaFuncAttributeMaxDynamicSharedMemorySize, ATT_SMEM);
    cudaFuncSetAttribute(attn_kernel<1>, cudaFuncAttributeMaxDynamicSharedMemorySize, ATT_SMEM);

    float *prefix, *h, *xn, *kvctx, *attn, *ff, *qkv, *w;
    cudaGetSymbolAddress((void**)&prefix, g_prefix);
    cudaGetSymbolAddress((void**)&h,      g_h);
    cudaGetSymbolAddress((void**)&xn,     g_xn);
    cudaGetSymbolAddress((void**)&kvctx,  g_kvctx);
    cudaGetSymbolAddress((void**)&attn,   g_attn);
    cudaGetSymbolAddress((void**)&ff,     g_ff);
    cudaGetSymbolAddress((void**)&qkv,    g_qkv);
    cudaGetSymbolAddress((void**)&w,      g_w);

    // 0. Pre-round / pack all weights to tf32 values (main stream, fused).
    {
        int n4 = (DMODEL * 3 * INNER) / 4;
        pack_cqkv_kernel<<<(n4 + 255) / 256, 256>>>(ca_wq, ca_wkv, w + W_CQKV);
    }
    {
        // Early weights: WKV 512, WO 256, CF1 1024, CF2 1024 blocks
        int e0 = 512, e1 = 768, e2 = 1792, e3 = 2816;
        round_multi_kernel<<<2816, 256>>>(
            ca_wkv, ca_wo, cf_w1, cf_w2, cf_w2, w + W_WKV, e0, e1, e2, e3);
    }
    {
        // Late weights: LQKV 3072, LWO 1024, LF1 4096, LF2 4096, LOG 8000
        int e0 = 3072, e1 = 4096, e2 = 8192, e3 = 12288;
        round_multi_kernel<<<20288, 256>>>(
            la_wqkv, la_wo, lf_w1, lf_w2, w_logits, w + W_LQKV, e0, e1, e2, e3);
    }

    // 1. Embedding (float4 vectorized)
    embed_kernel<<<(NCTX * DMODEL / 4) / 256, 256>>>(x, tok_emb, pos_emb);

    // 2. Cross-attention block (fused qkv projection)
    ln_kernel<<<LAT, 256>>>(h, xn, ca_ln_g, ca_ln_b);
    run_sgemm(0, xn,     w + W_CQKV, qkv,   nullptr, nullptr, LAT, 3 * INNER, DMODEL);
    run_sgemm(0, prefix, w + W_WKV,  kvctx, nullptr, nullptr, PFX, 2 * INNER, DMODEL);
    {
        dim3 gg(LAT / 64, NHEAD);
        attn_kernel<1><<<gg, 128, ATT_SMEM>>>(qkv, kvctx, attn);
    }
    run_sgemm(1, attn, w + W_WO, h, ca_bo, h, LAT, DMODEL, INNER);

    // 3. Cross FFN
    ln_kernel<<<LAT, 256>>>(h, xn, cf_ln_g, cf_ln_b);
    run_sgemm(3, xn, w + W_CF1, ff, nullptr, nullptr, LAT, FFDIM, DMODEL);
    run_sgemm(2, ff, w + W_CF2, h, nullptr, h, LAT, DMODEL, FFDIM);

    // 4. Latent self-attention layers
    for (int l = 0; l < DEPTH; l++) {
        ln_kernel<<<LAT, 256>>>(h, xn, la_ln_g + (size_t)l * DMODEL, la_ln_b + (size_t)l * DMODEL);
        run_sgemm(0, xn, w + W_LQKV + (size_t)l * DMODEL * 3 * INNER, qkv,
                  nullptr, nullptr, LAT, 3 * INNER, DMODEL);
        {
            dim3 gg(LAT / 64, NHEAD);
            attn_kernel<0><<<gg, 128, ATT_SMEM>>>(qkv, nullptr, attn);
        }
        run_sgemm(2, attn, w + W_LWO + (size_t)l * INNER * DMODEL, h, nullptr, h, LAT, DMODEL, INNER);

        ln_kernel<<<LAT, 256>>>(h, xn, lf_ln_g + (size_t)l * DMODEL, lf_ln_b + (size_t)l * DMODEL);
        run_sgemm(3, xn, w + W_LF1 + (size_t)l * DMODEL * FFDIM, ff, nullptr, nullptr, LAT, FFDIM, DMODEL);
        run_sgemm(2, ff, w + W_LF2 + (size_t)l * FFDIM * DMODEL, h, nullptr, h, LAT, DMODEL, FFDIM);
    }

    // 5. Logits (round h into xn first: h itself must stay fp32)
    round_kernel<<<(LAT * DMODEL / 4) / 1024, 256>>>(h, xn, LAT * DMODEL / 4);
    run_sgemm(0, xn, w + W_LOG, out, nullptr, nullptr, LAT, VOCAB, DMODEL);
}